// round 1
// baseline (speedup 1.0000x reference)
#include <cuda_runtime.h>
#include <cstdint>

// Problem constants
#define Bn 4
#define Cn 256
#define Hn 128
#define Wn 224
#define PD 4            // MAX_DISP
#define NDISP 9         // 2*PD+1

// Tiling
#define TH 8            // output rows per block
#define TW 32           // output cols per block
#define CC 8            // channels per pipeline stage
#define NK (Cn / CC)    // 32 stages
#define SROWS (TH + 2*PD)   // 16 second-tile rows
#define SCOLS (TW + 2*PD)   // 40 second-tile cols
#define NTHREADS 192    // (TH*TW/4 pixel-groups) * 3 dy-groups

#define S_STAGE (CC * SROWS * SCOLS)   // 5120 floats
#define F_STAGE (CC * TH * TW)         // 2048 floats
#define SMEM_FLOATS (2 * S_STAGE + 2 * F_STAGE)
#define SMEM_BYTES (SMEM_FLOATS * 4)   // 57344 B

typedef unsigned long long ull;

__device__ __forceinline__ uint32_t saddr(const void* p) {
    return (uint32_t)__cvta_generic_to_shared(p);
}
__device__ __forceinline__ void cpa4(uint32_t dst, const float* src, bool ok) {
    int sz = ok ? 4 : 0;
    asm volatile("cp.async.ca.shared.global [%0], [%1], 4, %2;\n"
                 :: "r"(dst), "l"(src), "r"(sz));
}
__device__ __forceinline__ void cpa16(uint32_t dst, const float* src) {
    asm volatile("cp.async.cg.shared.global [%0], [%1], 16;\n"
                 :: "r"(dst), "l"(src));
}
#define CP_COMMIT() asm volatile("cp.async.commit_group;\n" ::: "memory")
#define CP_WAIT1()  asm volatile("cp.async.wait_group 1;\n" ::: "memory")
#define CP_WAIT0()  asm volatile("cp.async.wait_group 0;\n" ::: "memory")

// pack two floats into one 64-bit reg (lane0 = lo, lane1 = hi)
#define PACK2(d, l0, h0) asm("mov.b64 %0, {%1, %2};" : "=l"(d) : "f"(l0), "f"(h0))
#define UNPACK2(l0, h0, s) asm("mov.b64 {%0, %1}, %2;" : "=f"(l0), "=f"(h0) : "l"(s))
// packed dual fp32 FMA (SASS FFMA2) — 2 FMAs per issue slot
#define FMA2(a, x, y) asm("fma.rn.f32x2 %0, %1, %2, %3;" : "=l"(a) : "l"(x), "l"(y), "l"(a))

__device__ __forceinline__ void load_stage(
    const float* __restrict__ sbase, const float* __restrict__ fbase,
    float* __restrict__ sS, float* __restrict__ fS,
    int stage, int c0, int y0, int x0g, int tid)
{
    // second tile with halo: rows [y0-4, y0+TH+4), cols [x0g-4, x0g+TW+4), zero-filled OOB
    float* sdst = sS + stage * S_STAGE;
    #pragma unroll
    for (int it = 0; it < (S_STAGE + NTHREADS - 1) / NTHREADS; it++) {
        int idx = tid + it * NTHREADS;
        if (idx < S_STAGE) {
            int j = idx % SCOLS;
            int t = idx / SCOLS;
            int i = t % SROWS;
            int c = t / SROWS;
            int gy = y0 - PD + i;
            int gx = x0g - PD + j;
            bool ok = ((unsigned)gy < (unsigned)Hn) && ((unsigned)gx < (unsigned)Wn);
            const float* src = sbase + ((size_t)(c0 + c) * Hn + (ok ? gy : 0)) * Wn + (ok ? gx : 0);
            cpa4(saddr(sdst + idx), src, ok);
        }
    }
    // first tile: always in-bounds, 16B aligned
    float* fdst = fS + stage * F_STAGE;
    #pragma unroll
    for (int it = 0; it < (F_STAGE / 4 + NTHREADS - 1) / NTHREADS; it++) {
        int idx = tid + it * NTHREADS;
        if (idx < F_STAGE / 4) {
            int j = (idx & 7) * 4;          // col (TW/4 = 8 groups)
            int i = (idx >> 3) & (TH - 1);  // row
            int c = idx >> 6;               // (idx / (8*TH))
            const float* src = fbase + ((size_t)(c0 + c) * Hn + (y0 + i)) * Wn + (x0g + j);
            cpa16(saddr(fdst + (c * TH + i) * TW + j), src);
        }
    }
    CP_COMMIT();
}

__global__ void __launch_bounds__(NTHREADS, 2)
corr_kernel(const float* __restrict__ first, const float* __restrict__ second,
            float* __restrict__ out)
{
    extern __shared__ float sm[];
    float* sS = sm;                   // [2][CC][SROWS][SCOLS]
    float* fS = sm + 2 * S_STAGE;     // [2][CC][TH][TW]

    const int tid = threadIdx.x;
    const int x0g = blockIdx.x * TW;
    const int y0  = blockIdx.y * TH;
    const int b   = blockIdx.z;

    // thread -> (dy-group g of {3g,3g+1,3g+2}, pixel row py, 4-pixel col group)
    const int g   = tid >> 6;          // 0..2
    const int pid = tid & 63;
    const int py  = pid >> 3;          // 0..7
    const int xo  = (pid & 7) * 4;     // 0,4,...,28

    const float* fbase = first  + (size_t)b * Cn * Hn * Wn;
    const float* sbase = second + (size_t)b * Cn * Hn * Wn;

    // 54 packed accumulators = 108 fp32 sums: [dy-in-group][dx][pixel-pair]
    ull acc[3][NDISP][2];
    #pragma unroll
    for (int r = 0; r < 3; r++)
        #pragma unroll
        for (int dx = 0; dx < NDISP; dx++) {
            acc[r][dx][0] = 0ull;
            acc[r][dx][1] = 0ull;
        }

    load_stage(sbase, fbase, sS, fS, 0, 0, y0, x0g, tid);

    #pragma unroll 1
    for (int kc = 0; kc < NK; kc++) {
        if (kc + 1 < NK) {
            load_stage(sbase, fbase, sS, fS, (kc + 1) & 1, (kc + 1) * CC, y0, x0g, tid);
            CP_WAIT1();
        } else {
            CP_WAIT0();
        }
        __syncthreads();

        const float* sC = sS + (kc & 1) * S_STAGE;
        const float* fC = fS + (kc & 1) * F_STAGE;

        #pragma unroll
        for (int c = 0; c < CC; c++) {
            float4 f4 = *(const float4*)(fC + (c * TH + py) * TW + xo);
            ull f2a, f2b;
            PACK2(f2a, f4.x, f4.y);
            PACK2(f2b, f4.z, f4.w);

            #pragma unroll
            for (int r = 0; r < 3; r++) {
                const int dy = 3 * g + r;
                const float* sr = sC + (c * SROWS + (py + dy)) * SCOLS + xo;
                float4 a0 = *(const float4*)(sr);
                float4 a1 = *(const float4*)(sr + 4);
                float4 a2 = *(const float4*)(sr + 8);
                float w0 = a0.x, w1 = a0.y, w2 = a0.z, w3 = a0.w;
                float w4 = a1.x, w5 = a1.y, w6 = a1.z, w7 = a1.w;
                float w8 = a2.x, w9 = a2.y, w10 = a2.z, w11 = a2.w;

                ull pr[11];
                PACK2(pr[0],  w0,  w1);
                PACK2(pr[1],  w1,  w2);
                PACK2(pr[2],  w2,  w3);
                PACK2(pr[3],  w3,  w4);
                PACK2(pr[4],  w4,  w5);
                PACK2(pr[5],  w5,  w6);
                PACK2(pr[6],  w6,  w7);
                PACK2(pr[7],  w7,  w8);
                PACK2(pr[8],  w8,  w9);
                PACK2(pr[9],  w9,  w10);
                PACK2(pr[10], w10, w11);

                #pragma unroll
                for (int dx = 0; dx < NDISP; dx++) {
                    FMA2(acc[r][dx][0], f2a, pr[dx]);       // pixels x, x+1
                    FMA2(acc[r][dx][1], f2b, pr[dx + 2]);   // pixels x+2, x+3
                }
            }
        }
        __syncthreads();
    }

    // epilogue: scale by 1/C and store 4 consecutive x per (dy,dx)
    const float inv = 1.0f / (float)Cn;
    #pragma unroll
    for (int r = 0; r < 3; r++) {
        const int dy = 3 * g + r;
        #pragma unroll
        for (int dx = 0; dx < NDISP; dx++) {
            float l0, h0, l1, h1;
            UNPACK2(l0, h0, acc[r][dx][0]);
            UNPACK2(l1, h1, acc[r][dx][1]);
            float4 o4 = make_float4(l0 * inv, h0 * inv, l1 * inv, h1 * inv);
            int d = dy * NDISP + dx;
            float* dst = out + (((size_t)b * (NDISP * NDISP) + d) * Hn + (y0 + py)) * Wn
                         + x0g + xo;
            *(float4*)dst = o4;
        }
    }
}

extern "C" void kernel_launch(void* const* d_in, const int* in_sizes, int n_in,
                              void* d_out, int out_size)
{
    const float* first  = (const float*)d_in[0];
    const float* second = (const float*)d_in[1];
    float* out = (float*)d_out;

    cudaFuncSetAttribute(corr_kernel, cudaFuncAttributeMaxDynamicSharedMemorySize, SMEM_BYTES);

    dim3 grid(Wn / TW, Hn / TH, Bn);   // 7 x 16 x 4 = 448 blocks
    corr_kernel<<<grid, NTHREADS, SMEM_BYTES>>>(first, second, out);
}

// round 6
// speedup vs baseline: 1.8241x; 1.8241x over previous
#include <cuda_runtime.h>
#include <cstdint>

// Problem constants
#define Bn 4
#define Cn 256
#define Hn 128
#define Wn 224
#define HW (Hn*Wn)          // 28672
#define PD 4
#define NDISP 9

// Tiling
#define TH 8
#define TW 16
#define CC 8                 // channels per stage
#define NK (Cn / CC)         // 32 stages
#define SROWS (TH + 2*PD)    // 16
#define SREAL (TW + 2*PD)    // 24 real cols
#define SCOLS 28             // padded (bank-conflict-free: 28 mod 32 coprime walk)
#define FCOLS 20             // first tile padded (16 real + 4)
#define NTHREADS 288         // 9 dy-groups x 32 (8 rows x 4 col-groups of 4 px)

#define S_STAGE (CC * SROWS * SCOLS)   // 3584 floats
#define F_STAGE (CC * TH * FCOLS)      // 1280 floats
#define S_BYTES (S_STAGE * 4)
#define F_BYTES (F_STAGE * 4)

#define CSTEP (CC * HW)      // gmem float advance per stage

typedef unsigned long long ull;

__device__ __forceinline__ uint32_t saddr(const void* p) {
    return (uint32_t)__cvta_generic_to_shared(p);
}
__device__ __forceinline__ void cpa16(uint32_t dst, const float* src, int sz) {
    asm volatile("cp.async.cg.shared.global [%0], [%1], 16, %2;\n"
                 :: "r"(dst), "l"(src), "r"(sz));
}
#define CP_COMMIT() asm volatile("cp.async.commit_group;\n" ::: "memory")
#define CP_WAIT1()  asm volatile("cp.async.wait_group 1;\n" ::: "memory")
#define CP_WAIT0()  asm volatile("cp.async.wait_group 0;\n" ::: "memory")

// (hi word of a, lo word of b) -> packed f32x2 pair (w_k, w_{k+1})
__device__ __forceinline__ ull mk(ull a, ull b) {
    ull r;
    asm("mov.b64 %0, {%1, %2};" : "=l"(r)
        : "r"((uint32_t)(a >> 32)), "r"((uint32_t)b));
    return r;
}
#define FMA2(a, x, y) asm("fma.rn.f32x2 %0, %1, %2, %0;" : "+l"(a) : "l"(x), "l"(y))
#define UNPACK2(l0, h0, s) asm("mov.b64 {%0, %1}, %2;" : "=f"(l0), "=f"(h0) : "l"(s))

__global__ void __launch_bounds__(NTHREADS, 2)
corr_kernel(const float* __restrict__ first, const float* __restrict__ second,
            float* __restrict__ out)
{
    __shared__ float sS[2 * S_STAGE];
    __shared__ float fS[2 * F_STAGE];

    const int tid = threadIdx.x;
    const int x0g = blockIdx.x * TW;
    const int y0  = blockIdx.y * TH;
    const int b   = blockIdx.z;

    const float* fbase = first  + (size_t)b * Cn * HW;
    const float* sbase = second + (size_t)b * Cn * HW;

    const uint32_t smemS = saddr(sS);
    const uint32_t smemF = saddr(fS);

    // ---- precompute loader slots (ONCE) ----
    // second tile: 8c x 16row x 6 chunks(16B) = 768 slots; threads cover 2-3 each
    const float* gp[3]; uint32_t so[3]; int sz[3];
    #pragma unroll
    for (int k = 0; k < 3; k++) {
        int s = tid + k * NTHREADS;
        if (s < CC * SROWS * (SREAL/4)) {
            int c   = s / (SROWS * (SREAL/4));
            int rem = s - c * (SROWS * (SREAL/4));
            int row = rem / (SREAL/4);
            int ch  = rem - row * (SREAL/4);
            int j   = ch * 4;
            int gy  = y0 - PD + row;
            int gx  = x0g - PD + j;
            bool ok = ((unsigned)gy < (unsigned)Hn) && ((unsigned)gx < (unsigned)Wn);
            gp[k] = sbase + ((size_t)c * Hn + (ok ? gy : 0)) * Wn + (ok ? gx : 0);
            so[k] = ((c * SROWS + row) * SCOLS + j) * 4;
            sz[k] = ok ? 16 : 0;
        } else {
            gp[k] = sbase; so[k] = 0; sz[k] = -1;  // inactive
        }
    }
    // first tile: 8c x 8row x 4 chunks = 256 slots (tid < 256)
    const float* gpF = fbase; uint32_t soF = 0; bool hasF = (tid < CC * TH * (TW/4));
    if (hasF) {
        int c   = tid >> 5;
        int rem = tid & 31;
        int row = rem >> 2;
        int j   = (rem & 3) * 4;
        gpF = fbase + ((size_t)c * Hn + (y0 + row)) * Wn + (x0g + j);
        soF = ((c * TH + row) * FCOLS + j) * 4;
    }

    #define ISSUE(buf) do {                                              \
        uint32_t sb_ = smemS + (buf) * S_BYTES;                          \
        if (sz[0] >= 0) { cpa16(sb_ + so[0], gp[0], sz[0]); gp[0] += CSTEP; } \
        if (sz[1] >= 0) { cpa16(sb_ + so[1], gp[1], sz[1]); gp[1] += CSTEP; } \
        if (sz[2] >= 0) { cpa16(sb_ + so[2], gp[2], sz[2]); gp[2] += CSTEP; } \
        if (hasF) { cpa16(smemF + (buf) * F_BYTES + soF, gpF, 16); gpF += CSTEP; } \
        CP_COMMIT();                                                     \
    } while (0)

    // ---- compute-thread mapping: g = dy (warp-uniform), quarter-warp = 8 rows ----
    const int g   = tid >> 5;            // 0..8  (= dy)
    const int pid = tid & 31;
    const int py  = pid & 7;             // row 0..7
    const int xo  = ((pid >> 3) & 3) * 4;// col group 0,4,8,12

    // 18 packed accumulators = 36 fp32: [dx][pixel-pair]
    ull acc[NDISP][2];
    #pragma unroll
    for (int dx = 0; dx < NDISP; dx++) { acc[dx][0] = 0ull; acc[dx][1] = 0ull; }

    ISSUE(0);

    const int srow_off = (py + g) * SCOLS + xo;   // within-channel second offset
    const int frow_off = py * FCOLS + xo;

    #pragma unroll 1
    for (int kc = 0; kc < NK; kc++) {
        if (kc + 1 < NK) { ISSUE((kc + 1) & 1); CP_WAIT1(); }
        else             { CP_WAIT0(); }
        __syncthreads();

        const float* sC = sS + (kc & 1) * S_STAGE;
        const float* fC = fS + (kc & 1) * F_STAGE;

        #pragma unroll
        for (int c = 0; c < CC; c++) {
            // first: 4 px -> 2 free f32x2 pairs
            const ulonglong2 fq = *(const ulonglong2*)(fC + c * (TH * FCOLS) + frow_off);
            ull f2a = fq.x, f2b = fq.y;

            // second: 12 floats -> q0..q5 (free even pairs)
            const ulonglong2* w = (const ulonglong2*)(sC + c * (SROWS * SCOLS) + srow_off);
            ulonglong2 A = w[0], B = w[1], C2 = w[2];
            ull q0 = A.x,  q1 = A.y,  q2 = B.x,  q3 = B.y,  q4 = C2.x, q5 = C2.y;

            ull pr1 = mk(q0, q1);
            ull pr3 = mk(q1, q2);
            ull pr5 = mk(q2, q3);
            ull pr7 = mk(q3, q4);
            ull pr9 = mk(q4, q5);

            ull pr[11] = {q0, pr1, q1, pr3, q2, pr5, q3, pr7, q4, pr9, q5};

            #pragma unroll
            for (int dx = 0; dx < NDISP; dx++) {
                FMA2(acc[dx][0], f2a, pr[dx]);       // pixels xo, xo+1
                FMA2(acc[dx][1], f2b, pr[dx + 2]);   // pixels xo+2, xo+3
            }
        }
        __syncthreads();
    }

    // ---- epilogue ----
    const float inv = 1.0f / (float)Cn;
    #pragma unroll
    for (int dx = 0; dx < NDISP; dx++) {
        float l0, h0, l1, h1;
        UNPACK2(l0, h0, acc[dx][0]);
        UNPACK2(l1, h1, acc[dx][1]);
        float4 o4 = make_float4(l0 * inv, h0 * inv, l1 * inv, h1 * inv);
        int d = g * NDISP + dx;
        float* dst = out + (((size_t)b * (NDISP * NDISP) + d) * HW)
                     + (y0 + py) * Wn + x0g + xo;
        *(float4*)dst = o4;
    }
}

extern "C" void kernel_launch(void* const* d_in, const int* in_sizes, int n_in,
                              void* d_out, int out_size)
{
    const float* first  = (const float*)d_in[0];
    const float* second = (const float*)d_in[1];
    float* out = (float*)d_out;

    dim3 grid(Wn / TW, Hn / TH, Bn);   // 14 x 16 x 4 = 896 blocks
    corr_kernel<<<grid, NTHREADS>>>(first, second, out);
}